// round 2
// baseline (speedup 1.0000x reference)
#include <cuda_runtime.h>
#include <cstddef>

// ---------------- problem constants ----------------
namespace {
constexpr int B = 8, T = 512, C = 1024, H = 16, E = 64, L = 2048;
constexpr int M = B * T;          // 4096 rows
constexpr int NKV = 3 * C;        // 3072
}

// ---------------- scratch (device globals; no allocation) ----------------
__device__ float g_q[(size_t)B * H * T * E];
__device__ float g_k[(size_t)B * H * T * E];
__device__ float g_v[(size_t)B * H * T * E];
__device__ float g_y[(size_t)M * C];

// ================= GEMM: 128x128 tile, BK=8, 256 threads, 8x8 micro =================
// SCATTER=true: epilogue scatters qkv columns into g_q/g_k/g_v (B,H,T,E) layout.
// SCATTER=false: plain C[r*N+c] = acc + bias[c]; if A==nullptr, reads g_y.
template<int N, bool SCATTER>
__global__ __launch_bounds__(256, 2) void gemm_kernel(
    const float* __restrict__ A, const float* __restrict__ W,
    const float* __restrict__ bias, float* __restrict__ out)
{
    constexpr int K = C;  // 1024
    __shared__ float As[8][128];
    __shared__ float Bs[8][128];

    const float* Abase = SCATTER ? A : (A ? A : g_y);

    const int tid = threadIdx.x;
    const int tx = tid & 15, ty = tid >> 4;
    const int bm = blockIdx.y * 128, bn = blockIdx.x * 128;

    float acc[8][8];
#pragma unroll
    for (int i = 0; i < 8; i++)
#pragma unroll
        for (int j = 0; j < 8; j++) acc[i][j] = 0.f;

    const int arow = tid >> 1, ak = (tid & 1) * 4;
    const int brow = tid >> 5, bcol = (tid & 31) * 4;
    const float* Ap = Abase + (size_t)(bm + arow) * K + ak;
    const float* Wp = W + (size_t)brow * N + bn + bcol;

    for (int k0 = 0; k0 < K; k0 += 8) {
        float4 a4 = *(const float4*)(Ap + k0);
        float4 b4 = *(const float4*)(Wp + (size_t)k0 * N);
        __syncthreads();
        As[ak + 0][arow] = a4.x;
        As[ak + 1][arow] = a4.y;
        As[ak + 2][arow] = a4.z;
        As[ak + 3][arow] = a4.w;
        *(float4*)&Bs[brow][bcol] = b4;
        __syncthreads();
#pragma unroll
        for (int kk = 0; kk < 8; kk++) {
            float4 a0 = *(const float4*)&As[kk][ty * 4];
            float4 a1 = *(const float4*)&As[kk][64 + ty * 4];
            float4 b0 = *(const float4*)&Bs[kk][tx * 4];
            float4 b1 = *(const float4*)&Bs[kk][64 + tx * 4];
            float av[8] = {a0.x, a0.y, a0.z, a0.w, a1.x, a1.y, a1.z, a1.w};
            float bv[8] = {b0.x, b0.y, b0.z, b0.w, b1.x, b1.y, b1.z, b1.w};
#pragma unroll
            for (int i = 0; i < 8; i++)
#pragma unroll
                for (int j = 0; j < 8; j++)
                    acc[i][j] = fmaf(av[i], bv[j], acc[i][j]);
        }
    }

#pragma unroll
    for (int i = 0; i < 8; i++) {
        int r = bm + ((i < 4) ? ty * 4 + i : 64 + ty * 4 + (i - 4));
#pragma unroll
        for (int j = 0; j < 8; j++) {
            int c = bn + ((j < 4) ? tx * 4 + j : 64 + tx * 4 + (j - 4));
            float v = acc[i][j] + bias[c];
            if (SCATTER) {
                int sel = c >> 10, w = c & 1023, hh = w >> 6, e = w & 63;
                float* dst = (sel == 0) ? g_q : (sel == 1) ? g_k : g_v;
                int bb = r >> 9, t = r & 511;
                dst[((size_t)(bb * H + hh) * T + t) * E + e] = v;
            } else {
                out[(size_t)r * N + c] = v;
            }
        }
    }
}

// ================= Flash attention =================
// Block: (tt, h, b). 128 q rows per block, 64-key chunks. 256 threads (16x16).
// S micro-tile: 8 rows x 4 cols. O micro-tile: 8 rows x 4 e-cols.
namespace {
constexpr int QT_STRIDE = 132;   // sQt[e][r], r in [0,128)
constexpr int KT_STRIDE = 68;    // sKt[e][s], s in [0,64)
constexpr int S_STRIDE  = 68;    // sS[r][s]
constexpr int SMEM_FLOATS = 64 * QT_STRIDE + 64 * KT_STRIDE + 128 * S_STRIDE + 64 * 64 + 3 * 128;
constexpr int SMEM_BYTES = SMEM_FLOATS * 4;  // 103936
}

__global__ __launch_bounds__(256, 2) void attn_kernel(
    const float* __restrict__ kcache, const float* __restrict__ vcache)
{
    extern __shared__ float sm[];
    float* sQt = sm;                        // [64][132]
    float* sKt = sQt + 64 * QT_STRIDE;      // [64][68]
    float* sS  = sKt + 64 * KT_STRIDE;      // [128][68]
    float* sV  = sS + 128 * S_STRIDE;       // [64][64]
    float* smM = sV + 64 * 64;              // [128]
    float* smL = smM + 128;                 // [128]
    float* smF = smL + 128;                 // [128]

    const int tid = threadIdx.x;
    const int tx = tid & 15, ty = tid >> 4;
    const int tt = blockIdx.x, hh = blockIdx.y, bb = blockIdx.z;

    const size_t bh = (size_t)bb * H + hh;
    const float* qsrc = g_q + (bh * T + (size_t)tt * 128) * E;
    const float* knew = g_k + bh * T * E;
    const float* vnew = g_v + bh * T * E;
    const float* kold = kcache + bh * L * E;
    const float* vold = vcache + bh * L * E;

    // load Q tile (128 x 64) transposed into sQt[e][r]
    {
        const int rb = tid >> 4;
        const int e4 = (tid & 15) * 4;
#pragma unroll
        for (int p = 0; p < 8; p++) {
            int r = p * 16 + rb;
            float4 q4 = *(const float4*)(qsrc + (size_t)r * E + e4);
            sQt[(e4 + 0) * QT_STRIDE + r] = q4.x;
            sQt[(e4 + 1) * QT_STRIDE + r] = q4.y;
            sQt[(e4 + 2) * QT_STRIDE + r] = q4.z;
            sQt[(e4 + 3) * QT_STRIDE + r] = q4.w;
        }
    }
    if (tid < 128) { smM[tid] = -1e30f; smL[tid] = 0.f; }

    float O[8][4];
#pragma unroll
    for (int i = 0; i < 8; i++)
#pragma unroll
        for (int j = 0; j < 4; j++) O[i][j] = 0.f;

    const int nch = 34 + 2 * tt;          // chunks of 64 keys
    const int limit = L + tt * 128;       // row r may attend j <= limit + r
    __syncthreads();

    for (int ch = 0; ch < nch; ch++) {
        const int j0 = ch * 64;
        // ---- load K (transposed) and V chunk ----
        {
            const int sb = tid >> 4;
            const int e4 = (tid & 15) * 4;
#pragma unroll
            for (int p = 0; p < 4; p++) {
                int s = p * 16 + sb;
                int j = j0 + s;
                const float* ks = (j < L) ? (kold + (size_t)j * E + e4)
                                          : (knew + (size_t)(j - L) * E + e4);
                const float* vs = (j < L) ? (vold + (size_t)j * E + e4)
                                          : (vnew + (size_t)(j - L) * E + e4);
                float4 k4 = *(const float4*)ks;
                sKt[(e4 + 0) * KT_STRIDE + s] = k4.x;
                sKt[(e4 + 1) * KT_STRIDE + s] = k4.y;
                sKt[(e4 + 2) * KT_STRIDE + s] = k4.z;
                sKt[(e4 + 3) * KT_STRIDE + s] = k4.w;
                *(float4*)&sV[s * 64 + e4] = *(const float4*)vs;
            }
        }
        __syncthreads();

        // ---- S = Q K^T ----
        float sacc[8][4];
#pragma unroll
        for (int i = 0; i < 8; i++)
#pragma unroll
            for (int j = 0; j < 4; j++) sacc[i][j] = 0.f;

#pragma unroll 16
        for (int e = 0; e < 64; e++) {
            float4 q0 = *(const float4*)&sQt[e * QT_STRIDE + ty * 4];
            float4 q1 = *(const float4*)&sQt[e * QT_STRIDE + 64 + ty * 4];
            float4 k4 = *(const float4*)&sKt[e * KT_STRIDE + tx * 4];
            float qv[8] = {q0.x, q0.y, q0.z, q0.w, q1.x, q1.y, q1.z, q1.w};
            float kv[4] = {k4.x, k4.y, k4.z, k4.w};
#pragma unroll
            for (int i = 0; i < 8; i++)
#pragma unroll
                for (int j = 0; j < 4; j++)
                    sacc[i][j] = fmaf(qv[i], kv[j], sacc[i][j]);
        }

        // ---- scale + (mask) + store to sS ----
        const bool domask = (ch >= nch - 2);
#pragma unroll
        for (int i = 0; i < 8; i++) {
            int r = (i < 4) ? ty * 4 + i : 64 + ty * 4 + (i - 4);
#pragma unroll
            for (int j = 0; j < 4; j++) {
                float v = sacc[i][j] * 0.125f;
                if (domask && (j0 + tx * 4 + j > limit + r)) v = -1e30f;
                sS[r * S_STRIDE + tx * 4 + j] = v;
            }
        }
        __syncthreads();

        // ---- online softmax: 2 threads per row ----
        {
            const int row = tid >> 1;
            float* rowp = &sS[row * S_STRIDE + (tid & 1) * 32];
            float mx = -1e30f;
#pragma unroll
            for (int c2 = 0; c2 < 32; c2++) mx = fmaxf(mx, rowp[c2]);
            mx = fmaxf(mx, __shfl_xor_sync(0xffffffffu, mx, 1));
            float mold = smM[row];
            float mnew = fmaxf(mold, mx);
            float ssum = 0.f;
#pragma unroll
            for (int c2 = 0; c2 < 32; c2++) {
                float p = __expf(rowp[c2] - mnew);
                rowp[c2] = p;
                ssum += p;
            }
            ssum += __shfl_xor_sync(0xffffffffu, ssum, 1);
            if (!(tid & 1)) {
                float f = __expf(mold - mnew);
                smF[row] = f;
                smM[row] = mnew;
                smL[row] = smL[row] * f + ssum;
            }
        }
        __syncthreads();

        // ---- rescale O, then O += P @ V ----
        {
            float fr[8];
#pragma unroll
            for (int i = 0; i < 4; i++) {
                fr[i] = smF[ty * 4 + i];
                fr[4 + i] = smF[64 + ty * 4 + i];
            }
#pragma unroll
            for (int i = 0; i < 8; i++)
#pragma unroll
                for (int j = 0; j < 4; j++) O[i][j] *= fr[i];

#pragma unroll 4
            for (int s4 = 0; s4 < 16; s4++) {
                float pv[8][4];
#pragma unroll
                for (int i = 0; i < 4; i++) {
                    float4 p0 = *(const float4*)&sS[(ty * 4 + i) * S_STRIDE + s4 * 4];
                    float4 p1 = *(const float4*)&sS[(64 + ty * 4 + i) * S_STRIDE + s4 * 4];
                    pv[i][0] = p0.x; pv[i][1] = p0.y; pv[i][2] = p0.z; pv[i][3] = p0.w;
                    pv[4 + i][0] = p1.x; pv[4 + i][1] = p1.y; pv[4 + i][2] = p1.z; pv[4 + i][3] = p1.w;
                }
#pragma unroll
                for (int ss = 0; ss < 4; ss++) {
                    float4 v4 = *(const float4*)&sV[(s4 * 4 + ss) * 64 + tx * 4];
#pragma unroll
                    for (int i = 0; i < 8; i++) {
                        O[i][0] = fmaf(pv[i][ss], v4.x, O[i][0]);
                        O[i][1] = fmaf(pv[i][ss], v4.y, O[i][1]);
                        O[i][2] = fmaf(pv[i][ss], v4.z, O[i][2]);
                        O[i][3] = fmaf(pv[i][ss], v4.w, O[i][3]);
                    }
                }
            }
        }
        __syncthreads();
    }

    // ---- epilogue: y in (B,T,C) layout ----
#pragma unroll
    for (int i = 0; i < 8; i++) {
        int r = (i < 4) ? ty * 4 + i : 64 + ty * 4 + (i - 4);
        float inv = 1.f / smL[r];
        int t = tt * 128 + r;
        float4 o4 = make_float4(O[i][0] * inv, O[i][1] * inv, O[i][2] * inv, O[i][3] * inv);
        *(float4*)&g_y[((size_t)(bb * T + t)) * C + hh * E + tx * 4] = o4;
    }
}

// ================= launch =================
extern "C" void kernel_launch(void* const* d_in, const int* in_sizes, int n_in,
                              void* d_out, int out_size)
{
    (void)in_sizes; (void)n_in; (void)out_size;
    const float* x      = (const float*)d_in[0];
    const float* kcache = (const float*)d_in[1];
    const float* vcache = (const float*)d_in[2];
    const float* Wqkv   = (const float*)d_in[3];
    const float* bqkv   = (const float*)d_in[4];
    const float* Wproj  = (const float*)d_in[5];
    const float* bproj  = (const float*)d_in[6];
    float* out = (float*)d_out;

    cudaFuncSetAttribute(attn_kernel, cudaFuncAttributeMaxDynamicSharedMemorySize, SMEM_BYTES);

    // 1) qkv projection, scattered into per-head q/k/v buffers
    gemm_kernel<NKV, true><<<dim3(NKV / 128, M / 128), 256>>>(x, Wqkv, bqkv, nullptr);
    // 2) causal attention over [cache | new] keys
    attn_kernel<<<dim3(T / 128, H, B), 256, SMEM_BYTES>>>(kcache, vcache);
    // 3) output projection (reads g_y internally via A==nullptr)
    gemm_kernel<C, false><<<dim3(C / 128, M / 128), 256>>>(nullptr, Wproj, bproj, out);
}

// round 3
// speedup vs baseline: 2.5618x; 2.5618x over previous
#include <cuda_runtime.h>
#include <cstdint>
#include <cstddef>

// ---------------- problem constants ----------------
namespace {
constexpr int B = 8, T = 512, C = 1024, H = 16, E = 64, L = 2048;
constexpr int M = B * T;          // 4096
constexpr int NKV = 3 * C;        // 3072
}

// ---------------- scratch (device globals; no allocation) ----------------
__device__ float g_q[(size_t)B * H * T * E];
__device__ float g_k[(size_t)B * H * T * E];
__device__ float g_v[(size_t)B * H * T * E];
__device__ float g_y[(size_t)M * C];

// ---------------- tf32 helpers ----------------
__device__ __forceinline__ uint32_t f2tf(float x) {
    uint32_t r;
    asm("cvt.rna.tf32.f32 %0, %1;" : "=r"(r) : "f"(x));
    return r;
}
__device__ __forceinline__ float f2tff(float x) { return __uint_as_float(f2tf(x)); }

__device__ __forceinline__ void mma_tf32(float* c, const uint32_t* a, const uint32_t* b) {
    asm volatile(
        "mma.sync.aligned.m16n8k8.row.col.f32.tf32.tf32.f32 "
        "{%0,%1,%2,%3}, {%4,%5,%6,%7}, {%8,%9}, {%0,%1,%2,%3};"
        : "+f"(c[0]), "+f"(c[1]), "+f"(c[2]), "+f"(c[3])
        : "r"(a[0]), "r"(a[1]), "r"(a[2]), "r"(a[3]), "r"(b[0]), "r"(b[1]));
}

// ================= tf32 tensor-core GEMM: 128x128 tile, BK=16, 256 thr =================
// warp grid 4(M) x 2(N); warp tile 32x64 = 2x8 m16n8k8 tiles.
template<int N, bool SCATTER>
__global__ __launch_bounds__(256, 2) void gemm_tc(
    const float* __restrict__ A_, const float* __restrict__ W,
    const float* __restrict__ bias, float* __restrict__ out)
{
    constexpr int K = C;                    // 1024
    __shared__ float As[128 * 20];          // [row][k] stride 20 (conflict-free)
    __shared__ float Bs[16 * 136];          // [k][col] stride 136 (conflict-free)

    const float* Abase = SCATTER ? A_ : (A_ ? A_ : g_y);

    const int tid = threadIdx.x;
    const int lane = tid & 31, warp = tid >> 5;
    const int l4 = lane >> 2, lq = lane & 3;
    const int wm = warp & 3, wn = warp >> 2;
    const int bm = blockIdx.y * 128, bn = blockIdx.x * 128;

    float acc[2][8][4];
#pragma unroll
    for (int mt = 0; mt < 2; mt++)
#pragma unroll
        for (int nt = 0; nt < 8; nt++)
#pragma unroll
            for (int i = 0; i < 4; i++) acc[mt][nt][i] = 0.f;

    const int ar = tid >> 2, ac = (tid & 3) * 4;   // A rows ar, ar+64; k-cols ac..ac+3
    const int br = tid >> 5, bc = (tid & 31) * 4;  // B k-rows br, br+8; cols bc..bc+3
    const float* Ap = Abase + (size_t)(bm + ar) * K + ac;
    const float* Wp = W + (size_t)br * N + bn + bc;

    float4 pa0 = *(const float4*)(Ap);
    float4 pa1 = *(const float4*)(Ap + (size_t)64 * K);
    float4 pb0 = *(const float4*)(Wp);
    float4 pb1 = *(const float4*)(Wp + (size_t)8 * N);

    for (int k0 = 0; k0 < K; k0 += 16) {
        // stage current prefetch into smem (tf32-rounded)
        As[ar * 20 + ac + 0] = f2tff(pa0.x);
        As[ar * 20 + ac + 1] = f2tff(pa0.y);
        As[ar * 20 + ac + 2] = f2tff(pa0.z);
        As[ar * 20 + ac + 3] = f2tff(pa0.w);
        As[(ar + 64) * 20 + ac + 0] = f2tff(pa1.x);
        As[(ar + 64) * 20 + ac + 1] = f2tff(pa1.y);
        As[(ar + 64) * 20 + ac + 2] = f2tff(pa1.z);
        As[(ar + 64) * 20 + ac + 3] = f2tff(pa1.w);
        Bs[br * 136 + bc + 0] = f2tff(pb0.x);
        Bs[br * 136 + bc + 1] = f2tff(pb0.y);
        Bs[br * 136 + bc + 2] = f2tff(pb0.z);
        Bs[br * 136 + bc + 3] = f2tff(pb0.w);
        Bs[(br + 8) * 136 + bc + 0] = f2tff(pb1.x);
        Bs[(br + 8) * 136 + bc + 1] = f2tff(pb1.y);
        Bs[(br + 8) * 136 + bc + 2] = f2tff(pb1.z);
        Bs[(br + 8) * 136 + bc + 3] = f2tff(pb1.w);
        __syncthreads();

        if (k0 + 16 < K) {  // prefetch next stage (overlaps with compute)
            pa0 = *(const float4*)(Ap + k0 + 16);
            pa1 = *(const float4*)(Ap + (size_t)64 * K + k0 + 16);
            pb0 = *(const float4*)(Wp + (size_t)(k0 + 16) * N);
            pb1 = *(const float4*)(Wp + (size_t)(k0 + 24) * N);
        }

#pragma unroll
        for (int kk = 0; kk < 16; kk += 8) {
            uint32_t a[2][4];
#pragma unroll
            for (int mt = 0; mt < 2; mt++) {
                int row = wm * 32 + mt * 16 + l4;
                a[mt][0] = __float_as_uint(As[row * 20 + kk + lq]);
                a[mt][1] = __float_as_uint(As[(row + 8) * 20 + kk + lq]);
                a[mt][2] = __float_as_uint(As[row * 20 + kk + 4 + lq]);
                a[mt][3] = __float_as_uint(As[(row + 8) * 20 + kk + 4 + lq]);
            }
#pragma unroll
            for (int nt = 0; nt < 8; nt++) {
                int col = wn * 64 + nt * 8 + l4;
                uint32_t b[2];
                b[0] = __float_as_uint(Bs[(kk + lq) * 136 + col]);
                b[1] = __float_as_uint(Bs[(kk + 4 + lq) * 136 + col]);
                mma_tf32(acc[0][nt], a[0], b);
                mma_tf32(acc[1][nt], a[1], b);
            }
        }
        __syncthreads();
    }

    // epilogue: c0=(r,c) c1=(r,c+1) c2=(r+8,c) c3=(r+8,c+1)
#pragma unroll
    for (int mt = 0; mt < 2; mt++) {
        int r0 = bm + wm * 32 + mt * 16 + l4;
#pragma unroll
        for (int nt = 0; nt < 8; nt++) {
            int c0 = bn + wn * 64 + nt * 8 + 2 * lq;
            float v00 = acc[mt][nt][0] + bias[c0];
            float v01 = acc[mt][nt][1] + bias[c0 + 1];
            float v10 = acc[mt][nt][2] + bias[c0];
            float v11 = acc[mt][nt][3] + bias[c0 + 1];
            if (SCATTER) {
#pragma unroll
                for (int e2 = 0; e2 < 4; e2++) {
                    int r = (e2 & 2) ? r0 + 8 : r0;
                    int c = c0 + (e2 & 1);
                    float v = (e2 == 0) ? v00 : (e2 == 1) ? v01 : (e2 == 2) ? v10 : v11;
                    int sel = c >> 10, w = c & 1023, hh = w >> 6, e = w & 63;
                    float* dst = (sel == 0) ? g_q : (sel == 1) ? g_k : g_v;
                    int bb = r >> 9, t = r & 511;
                    dst[((size_t)(bb * H + hh) * T + t) * E + e] = v;
                }
            } else {
                *(float2*)&out[(size_t)r0 * N + c0] = make_float2(v00, v01);
                *(float2*)&out[(size_t)(r0 + 8) * N + c0] = make_float2(v10, v11);
            }
        }
    }
}

// ================= tf32 tensor-core flash attention =================
// Block (tt,h,b): 128 q rows, 8 warps x 16 rows. 64-key chunks.
namespace {
constexpr int ATT_SMEM_FLOATS = 128 * 68 + 64 * 68 + 64 * 68;  // sQ, sK, sVt
constexpr int ATT_SMEM_BYTES = ATT_SMEM_FLOATS * 4;            // 69632
}

__global__ __launch_bounds__(256, 2) void attn_tc(
    const float* __restrict__ kcache, const float* __restrict__ vcache)
{
    extern __shared__ float sm[];
    float* sQ = sm;                 // [128][68] row x e
    float* sK = sQ + 128 * 68;      // [64][68]  key x e
    float* sVt = sK + 64 * 68;      // [64][68]  e x key

    const int tid = threadIdx.x;
    const int lane = tid & 31, warp = tid >> 5;
    const int l4 = lane >> 2, lq = lane & 3;
    const int tt = blockIdx.x, hh = blockIdx.y, bb = blockIdx.z;

    const size_t bh = (size_t)bb * H + hh;
    const float* qsrc = g_q + (bh * T + (size_t)tt * 128) * E;
    const float* knew = g_k + bh * T * E;
    const float* vnew = g_v + bh * T * E;
    const float* kold = kcache + bh * L * E;
    const float* vold = vcache + bh * L * E;

    // load Q tile (tf32-rounded)
#pragma unroll
    for (int p = 0; p < 8; p++) {
        int idx = p * 256 + tid;
        int r = idx >> 4, e4 = (idx & 15) * 4;
        float4 q4 = *(const float4*)(qsrc + (size_t)r * E + e4);
        *(float4*)&sQ[r * 68 + e4] =
            make_float4(f2tff(q4.x), f2tff(q4.y), f2tff(q4.z), f2tff(q4.w));
    }

    float m0 = -1e30f, m1 = -1e30f, l0 = 0.f, l1 = 0.f;
    float O[8][4];
#pragma unroll
    for (int nt = 0; nt < 8; nt++)
#pragma unroll
        for (int i = 0; i < 4; i++) O[nt][i] = 0.f;

    const int wrow = warp * 16;
    const int nch = 34 + 2 * tt;
    const int lim0 = L + tt * 128 + wrow + l4;   // row r0 may see j <= lim0
    const int src_lo = (lane & ~3) | (lq >> 1);
    const int src_hi = src_lo + 2;
    const bool odd = lq & 1;

    for (int ch = 0; ch < nch; ch++) {
        const int j0 = ch * 64;
        __syncthreads();   // previous chunk's reads done before overwriting K/V
        // ---- load K chunk and transposed V chunk (tf32-rounded) ----
#pragma unroll
        for (int p = 0; p < 4; p++) {
            int idx = p * 256 + tid;
            int s = idx >> 4, e4 = (idx & 15) * 4;
            int j = j0 + s;
            const float* ks = (j < L) ? (kold + (size_t)j * E + e4)
                                      : (knew + (size_t)(j - L) * E + e4);
            const float* vs = (j < L) ? (vold + (size_t)j * E + e4)
                                      : (vnew + (size_t)(j - L) * E + e4);
            float4 k4 = *(const float4*)ks;
            *(float4*)&sK[s * 68 + e4] =
                make_float4(f2tff(k4.x), f2tff(k4.y), f2tff(k4.z), f2tff(k4.w));
            float4 v4 = *(const float4*)vs;
            sVt[(e4 + 0) * 68 + s] = f2tff(v4.x);
            sVt[(e4 + 1) * 68 + s] = f2tff(v4.y);
            sVt[(e4 + 2) * 68 + s] = f2tff(v4.z);
            sVt[(e4 + 3) * 68 + s] = f2tff(v4.w);
        }
        __syncthreads();

        // ---- S = Q K^T (warp: 16 rows x 64 keys) ----
        float sc[8][4];
#pragma unroll
        for (int nt = 0; nt < 8; nt++)
#pragma unroll
            for (int i = 0; i < 4; i++) sc[nt][i] = 0.f;

#pragma unroll
        for (int kk = 0; kk < 64; kk += 8) {
            uint32_t a[4];
            a[0] = __float_as_uint(sQ[(wrow + l4) * 68 + kk + lq]);
            a[1] = __float_as_uint(sQ[(wrow + 8 + l4) * 68 + kk + lq]);
            a[2] = __float_as_uint(sQ[(wrow + l4) * 68 + kk + 4 + lq]);
            a[3] = __float_as_uint(sQ[(wrow + 8 + l4) * 68 + kk + 4 + lq]);
#pragma unroll
            for (int nt = 0; nt < 8; nt++) {
                uint32_t b[2];
                b[0] = __float_as_uint(sK[(nt * 8 + l4) * 68 + kk + lq]);
                b[1] = __float_as_uint(sK[(nt * 8 + l4) * 68 + kk + 4 + lq]);
                mma_tf32(sc[nt], a, b);
            }
        }

        // ---- scale + causal mask (only last 2 chunks touch the diagonal) ----
#pragma unroll
        for (int nt = 0; nt < 8; nt++)
#pragma unroll
            for (int i = 0; i < 4; i++) sc[nt][i] *= 0.125f;
        if (ch >= nch - 2) {
#pragma unroll
            for (int nt = 0; nt < 8; nt++) {
                int cb = j0 + nt * 8 + 2 * lq;
                if (cb > lim0)         sc[nt][0] = -1e30f;
                if (cb + 1 > lim0)     sc[nt][1] = -1e30f;
                if (cb > lim0 + 8)     sc[nt][2] = -1e30f;
                if (cb + 1 > lim0 + 8) sc[nt][3] = -1e30f;
            }
        }

        // ---- register-resident online softmax (rows r0=l4, r1=l4+8) ----
        float mx0 = -1e30f, mx1 = -1e30f;
#pragma unroll
        for (int nt = 0; nt < 8; nt++) {
            mx0 = fmaxf(mx0, fmaxf(sc[nt][0], sc[nt][1]));
            mx1 = fmaxf(mx1, fmaxf(sc[nt][2], sc[nt][3]));
        }
        mx0 = fmaxf(mx0, __shfl_xor_sync(0xffffffffu, mx0, 1));
        mx0 = fmaxf(mx0, __shfl_xor_sync(0xffffffffu, mx0, 2));
        mx1 = fmaxf(mx1, __shfl_xor_sync(0xffffffffu, mx1, 1));
        mx1 = fmaxf(mx1, __shfl_xor_sync(0xffffffffu, mx1, 2));
        float mn0 = fmaxf(m0, mx0), mn1 = fmaxf(m1, mx1);
        float sum0 = 0.f, sum1 = 0.f;
#pragma unroll
        for (int nt = 0; nt < 8; nt++) {
            sc[nt][0] = __expf(sc[nt][0] - mn0); sum0 += sc[nt][0];
            sc[nt][1] = __expf(sc[nt][1] - mn0); sum0 += sc[nt][1];
            sc[nt][2] = __expf(sc[nt][2] - mn1); sum1 += sc[nt][2];
            sc[nt][3] = __expf(sc[nt][3] - mn1); sum1 += sc[nt][3];
        }
        sum0 += __shfl_xor_sync(0xffffffffu, sum0, 1);
        sum0 += __shfl_xor_sync(0xffffffffu, sum0, 2);
        sum1 += __shfl_xor_sync(0xffffffffu, sum1, 1);
        sum1 += __shfl_xor_sync(0xffffffffu, sum1, 2);
        float f0 = __expf(m0 - mn0), f1 = __expf(m1 - mn1);
        l0 = l0 * f0 + sum0; l1 = l1 * f1 + sum1;
        m0 = mn0; m1 = mn1;
#pragma unroll
        for (int nt = 0; nt < 8; nt++) {
            O[nt][0] *= f0; O[nt][1] *= f0; O[nt][2] *= f1; O[nt][3] *= f1;
        }

        // ---- O += P @ V : P C-frags -> A-frags via quad shfl, V^T from smem ----
#pragma unroll
        for (int kt = 0; kt < 8; kt++) {
            uint32_t a[4];
            {
                float v0 = __shfl_sync(0xffffffffu, sc[kt][0], src_lo);
                float v1 = __shfl_sync(0xffffffffu, sc[kt][1], src_lo);
                a[0] = f2tf(odd ? v1 : v0);
                v0 = __shfl_sync(0xffffffffu, sc[kt][0], src_hi);
                v1 = __shfl_sync(0xffffffffu, sc[kt][1], src_hi);
                a[2] = f2tf(odd ? v1 : v0);
                v0 = __shfl_sync(0xffffffffu, sc[kt][2], src_lo);
                v1 = __shfl_sync(0xffffffffu, sc[kt][3], src_lo);
                a[1] = f2tf(odd ? v1 : v0);
                v0 = __shfl_sync(0xffffffffu, sc[kt][2], src_hi);
                v1 = __shfl_sync(0xffffffffu, sc[kt][3], src_hi);
                a[3] = f2tf(odd ? v1 : v0);
            }
#pragma unroll
            for (int nt = 0; nt < 8; nt++) {
                uint32_t b[2];
                b[0] = __float_as_uint(sVt[(nt * 8 + l4) * 68 + kt * 8 + lq]);
                b[1] = __float_as_uint(sVt[(nt * 8 + l4) * 68 + kt * 8 + 4 + lq]);
                mma_tf32(O[nt], a, b);
            }
        }
    }

    // ---- epilogue: y in (B,T,C) ----
    float inv0 = 1.f / l0, inv1 = 1.f / l1;
    int t0 = tt * 128 + wrow + l4;
#pragma unroll
    for (int nt = 0; nt < 8; nt++) {
        int cc = hh * 64 + nt * 8 + 2 * lq;
        *(float2*)&g_y[(size_t)(bb * T + t0) * C + cc] =
            make_float2(O[nt][0] * inv0, O[nt][1] * inv0);
        *(float2*)&g_y[(size_t)(bb * T + t0 + 8) * C + cc] =
            make_float2(O[nt][2] * inv1, O[nt][3] * inv1);
    }
}

// ================= launch =================
extern "C" void kernel_launch(void* const* d_in, const int* in_sizes, int n_in,
                              void* d_out, int out_size)
{
    (void)in_sizes; (void)n_in; (void)out_size;
    const float* x      = (const float*)d_in[0];
    const float* kcache = (const float*)d_in[1];
    const float* vcache = (const float*)d_in[2];
    const float* Wqkv   = (const float*)d_in[3];
    const float* bqkv   = (const float*)d_in[4];
    const float* Wproj  = (const float*)d_in[5];
    const float* bproj  = (const float*)d_in[6];
    float* out = (float*)d_out;

    cudaFuncSetAttribute(attn_tc, cudaFuncAttributeMaxDynamicSharedMemorySize, ATT_SMEM_BYTES);

    gemm_tc<NKV, true><<<dim3(NKV / 128, M / 128), 256>>>(x, Wqkv, bqkv, nullptr);
    attn_tc<<<dim3(T / 128, H, B), 256, ATT_SMEM_BYTES>>>(kcache, vcache);
    gemm_tc<C, false><<<dim3(C / 128, M / 128), 256>>>(nullptr, Wproj, bproj, out);
}

// round 5
// speedup vs baseline: 2.8040x; 1.0945x over previous
#include <cuda_runtime.h>
#include <cstdint>
#include <cstddef>

// ---------------- problem constants ----------------
namespace {
constexpr int B = 8, T = 512, C = 1024, H = 16, E = 64, L = 2048;
constexpr int M = B * T;          // 4096
constexpr int NKV = 3 * C;        // 3072
}

// ---------------- scratch (device globals; no allocation) ----------------
__device__ float g_q[(size_t)B * H * T * E];
__device__ float g_k[(size_t)B * H * T * E];
__device__ float g_v[(size_t)B * H * T * E];
__device__ float g_y[(size_t)M * C];

// ---------------- helpers ----------------
__device__ __forceinline__ uint32_t f2tf(float x) {
    uint32_t r;
    asm("cvt.rna.tf32.f32 %0, %1;" : "=r"(r) : "f"(x));
    return r;
}

__device__ __forceinline__ void mma_tf32(float* c, const uint32_t* a, const uint32_t* b) {
    asm volatile(
        "mma.sync.aligned.m16n8k8.row.col.f32.tf32.tf32.f32 "
        "{%0,%1,%2,%3}, {%4,%5,%6,%7}, {%8,%9}, {%0,%1,%2,%3};"
        : "+f"(c[0]), "+f"(c[1]), "+f"(c[2]), "+f"(c[3])
        : "r"(a[0]), "r"(a[1]), "r"(a[2]), "r"(a[3]), "r"(b[0]), "r"(b[1]));
}

__device__ __forceinline__ void cp16(float* dst_smem, const float* src) {
    uint32_t a = (uint32_t)__cvta_generic_to_shared(dst_smem);
    asm volatile("cp.async.cg.shared.global [%0], [%1], 16;" :: "r"(a), "l"(src));
}
#define CP_COMMIT asm volatile("cp.async.commit_group;")
template<int NN> __device__ __forceinline__ void cp_wait() {
    asm volatile("cp.async.wait_group %0;" :: "n"(NN));
}

// ================= tf32 GEMM: 128x128 tile, BK=16, 128 thr, 4 warps (2x2), warp 64x64 =================
namespace {
constexpr int AS_STAGE = 128 * 36;   // [row][k] stride 36 (conflict-free, 16B rows)
constexpr int BS_STAGE = 16 * 136;   // [k][col] stride 136
constexpr int GEMM_SMEM = (2 * AS_STAGE + 2 * BS_STAGE) * 4;  // 54272 B
}

template<int N, bool SCATTER>
__global__ __launch_bounds__(128, 2) void gemm_tc(
    const float* __restrict__ A_, const float* __restrict__ W,
    const float* __restrict__ bias, float* __restrict__ out)
{
    constexpr int K = C;  // 1024
    extern __shared__ float smg[];
    float* As = smg;                  // [2][128][36]
    float* Bs = smg + 2 * AS_STAGE;   // [2][16][136]

    const float* Abase = SCATTER ? A_ : (A_ ? A_ : g_y);

    const int tid = threadIdx.x;
    const int lane = tid & 31, warp = tid >> 5;
    const int l4 = lane >> 2, lq = lane & 3;
    const int wm = warp & 1, wn = warp >> 1;
    const int bm = blockIdx.y * 128, bn = blockIdx.x * 128;

    float acc[4][8][4];
#pragma unroll
    for (int mt = 0; mt < 4; mt++)
#pragma unroll
        for (int nt = 0; nt < 8; nt++)
#pragma unroll
            for (int i = 0; i < 4; i++) acc[mt][nt][i] = 0.f;

    auto stage = [&](int k0, int s) {
#pragma unroll
        for (int i = 0; i < 4; i++) {       // A: 128 rows x 16 k = 512 x 16B
            int c = tid + i * 128;
            int r = c >> 2, k4 = (c & 3) * 4;
            cp16(&As[s * AS_STAGE + r * 36 + k4],
                 Abase + (size_t)(bm + r) * K + k0 + k4);
        }
#pragma unroll
        for (int i = 0; i < 4; i++) {       // B: 16 k x 128 cols = 512 x 16B
            int c = tid + i * 128;
            int k = c >> 5, c4 = (c & 31) * 4;
            cp16(&Bs[s * BS_STAGE + k * 136 + c4],
                 W + (size_t)(k0 + k) * N + bn + c4);
        }
        CP_COMMIT;
    };

    stage(0, 0);

    for (int it = 0; it < K / 16; it++) {
        if (it + 1 < K / 16) { stage((it + 1) * 16, (it + 1) & 1); cp_wait<1>(); }
        else cp_wait<0>();
        __syncthreads();
        const float* a_s = As + (it & 1) * AS_STAGE;
        const float* b_s = Bs + (it & 1) * BS_STAGE;
#pragma unroll
        for (int kk = 0; kk < 16; kk += 8) {
            uint32_t a[4][4], b[8][2];
#pragma unroll
            for (int mt = 0; mt < 4; mt++) {
                int row = wm * 64 + mt * 16 + l4;
                a[mt][0] = f2tf(a_s[row * 36 + kk + lq]);
                a[mt][1] = f2tf(a_s[(row + 8) * 36 + kk + lq]);
                a[mt][2] = f2tf(a_s[row * 36 + kk + 4 + lq]);
                a[mt][3] = f2tf(a_s[(row + 8) * 36 + kk + 4 + lq]);
            }
#pragma unroll
            for (int nt = 0; nt < 8; nt++) {
                int col = wn * 64 + nt * 8 + l4;
                b[nt][0] = f2tf(b_s[(kk + lq) * 136 + col]);
                b[nt][1] = f2tf(b_s[(kk + 4 + lq) * 136 + col]);
            }
#pragma unroll
            for (int mt = 0; mt < 4; mt++)
#pragma unroll
                for (int nt = 0; nt < 8; nt++)
                    mma_tf32(acc[mt][nt], a[mt], b[nt]);
        }
        __syncthreads();
    }

    // epilogue
#pragma unroll
    for (int mt = 0; mt < 4; mt++) {
        int r0 = bm + wm * 64 + mt * 16 + l4;
#pragma unroll
        for (int nt = 0; nt < 8; nt++) {
            int c0 = bn + wn * 64 + nt * 8 + 2 * lq;
            float v00 = acc[mt][nt][0] + bias[c0];
            float v01 = acc[mt][nt][1] + bias[c0 + 1];
            float v10 = acc[mt][nt][2] + bias[c0];
            float v11 = acc[mt][nt][3] + bias[c0 + 1];
            if (SCATTER) {
                int sel = c0 >> 10, w = c0 & 1023, hh = w >> 6, e = w & 63;
                float* dst = (sel == 0) ? g_q : (sel == 1) ? g_k : g_v;
                int b0r = r0 >> 9, t0 = r0 & 511;
                int b1r = (r0 + 8) >> 9, t1 = (r0 + 8) & 511;
                *(float2*)&dst[((size_t)(b0r * H + hh) * T + t0) * E + e] = make_float2(v00, v01);
                *(float2*)&dst[((size_t)(b1r * H + hh) * T + t1) * E + e] = make_float2(v10, v11);
            } else {
                *(float2*)&out[(size_t)r0 * N + c0] = make_float2(v00, v01);
                *(float2*)&out[(size_t)(r0 + 8) * N + c0] = make_float2(v10, v11);
            }
        }
    }
}

// ================= tf32 flash attention, cp.async double-buffered =================
namespace {
constexpr int KV_STAGE = 64 * 68;
constexpr int ATT_SMEM = (128 * 68 + 4 * KV_STAGE) * 4;  // 104448 B
}

__global__ __launch_bounds__(256, 2) void attn_tc(
    const float* __restrict__ kcache, const float* __restrict__ vcache)
{
    extern __shared__ float sm[];
    float* sQ = sm;                       // [128][68]
    float* sK = sm + 128 * 68;            // [2][64][68]
    float* sV = sK + 2 * KV_STAGE;        // [2][64][68]

    const int tid = threadIdx.x;
    const int lane = tid & 31, warp = tid >> 5;
    const int l4 = lane >> 2, lq = lane & 3;
    const int tt = blockIdx.x, hh = blockIdx.y, bb = blockIdx.z;

    const size_t bh = (size_t)bb * H + hh;
    const float* qsrc = g_q + (bh * T + (size_t)tt * 128) * E;
    const float* knew = g_k + bh * T * E;
    const float* vnew = g_v + bh * T * E;
    const float* kold = kcache + bh * L * E;
    const float* vold = vcache + bh * L * E;

    auto issue_kv = [&](int ch, int s) {
        const float* kb = (ch < 32) ? kold + (size_t)ch * 64 * E
                                    : knew + ((size_t)ch * 64 - L) * E;
        const float* vb = (ch < 32) ? vold + (size_t)ch * 64 * E
                                    : vnew + ((size_t)ch * 64 - L) * E;
        float* dk = sK + s * KV_STAGE;
        float* dv = sV + s * KV_STAGE;
#pragma unroll
        for (int i = 0; i < 4; i++) {     // 64 rows x 64 e = 1024 x 16B each
            int c = tid + i * 256;
            int r = c >> 4, e4 = (c & 15) * 4;
            cp16(&dk[r * 68 + e4], kb + r * 64 + e4);
            cp16(&dv[r * 68 + e4], vb + r * 64 + e4);
        }
    };

    // prologue: Q + chunk 0 in one group
#pragma unroll
    for (int i = 0; i < 8; i++) {
        int c = tid + i * 256;
        int r = c >> 4, e4 = (c & 15) * 4;
        cp16(&sQ[r * 68 + e4], qsrc + (size_t)r * E + e4);
    }
    issue_kv(0, 0);
    CP_COMMIT;

    float m0 = -1e30f, m1 = -1e30f, l0 = 0.f, l1 = 0.f;
    float O[8][4];
#pragma unroll
    for (int nt = 0; nt < 8; nt++)
#pragma unroll
        for (int i = 0; i < 4; i++) O[nt][i] = 0.f;

    const int wrow = warp * 16;
    const int nch = 34 + 2 * tt;
    const int lim0 = L + tt * 128 + wrow + l4;
    const int src_lo = (lane & ~3) | (lq >> 1);
    const int src_hi = src_lo + 2;
    const bool odd = lq & 1;

    for (int ch = 0; ch < nch; ch++) {
        if (ch + 1 < nch) { issue_kv(ch + 1, (ch + 1) & 1); CP_COMMIT; cp_wait<1>(); }
        else cp_wait<0>();
        __syncthreads();
        const float* k_s = sK + (ch & 1) * KV_STAGE;
        const float* v_s = sV + (ch & 1) * KV_STAGE;
        const int j0 = ch * 64;

        // ---- S = Q K^T ----
        float sc[8][4];
#pragma unroll
        for (int nt = 0; nt < 8; nt++)
#pragma unroll
            for (int i = 0; i < 4; i++) sc[nt][i] = 0.f;

#pragma unroll
        for (int kk = 0; kk < 64; kk += 8) {
            uint32_t a[4];
            a[0] = f2tf(sQ[(wrow + l4) * 68 + kk + lq]);
            a[1] = f2tf(sQ[(wrow + 8 + l4) * 68 + kk + lq]);
            a[2] = f2tf(sQ[(wrow + l4) * 68 + kk + 4 + lq]);
            a[3] = f2tf(sQ[(wrow + 8 + l4) * 68 + kk + 4 + lq]);
#pragma unroll
            for (int nt = 0; nt < 8; nt++) {
                uint32_t b[2];
                b[0] = f2tf(k_s[(nt * 8 + l4) * 68 + kk + lq]);
                b[1] = f2tf(k_s[(nt * 8 + l4) * 68 + kk + 4 + lq]);
                mma_tf32(sc[nt], a, b);
            }
        }

        // ---- scale + causal mask ----
#pragma unroll
        for (int nt = 0; nt < 8; nt++)
#pragma unroll
            for (int i = 0; i < 4; i++) sc[nt][i] *= 0.125f;
        if (ch >= nch - 2) {
#pragma unroll
            for (int nt = 0; nt < 8; nt++) {
                int cb = j0 + nt * 8 + 2 * lq;
                if (cb > lim0)         sc[nt][0] = -1e30f;
                if (cb + 1 > lim0)     sc[nt][1] = -1e30f;
                if (cb > lim0 + 8)     sc[nt][2] = -1e30f;
                if (cb + 1 > lim0 + 8) sc[nt][3] = -1e30f;
            }
        }

        // ---- register-resident online softmax ----
        float mx0 = -1e30f, mx1 = -1e30f;
#pragma unroll
        for (int nt = 0; nt < 8; nt++) {
            mx0 = fmaxf(mx0, fmaxf(sc[nt][0], sc[nt][1]));
            mx1 = fmaxf(mx1, fmaxf(sc[nt][2], sc[nt][3]));
        }
        mx0 = fmaxf(mx0, __shfl_xor_sync(0xffffffffu, mx0, 1));
        mx0 = fmaxf(mx0, __shfl_xor_sync(0xffffffffu, mx0, 2));
        mx1 = fmaxf(mx1, __shfl_xor_sync(0xffffffffu, mx1, 1));
        mx1 = fmaxf(mx1, __shfl_xor_sync(0xffffffffu, mx1, 2));
        float mn0 = fmaxf(m0, mx0), mn1 = fmaxf(m1, mx1);
        float sum0 = 0.f, sum1 = 0.f;
#pragma unroll
        for (int nt = 0; nt < 8; nt++) {
            sc[nt][0] = __expf(sc[nt][0] - mn0); sum0 += sc[nt][0];
            sc[nt][1] = __expf(sc[nt][1] - mn0); sum0 += sc[nt][1];
            sc[nt][2] = __expf(sc[nt][2] - mn1); sum1 += sc[nt][2];
            sc[nt][3] = __expf(sc[nt][3] - mn1); sum1 += sc[nt][3];
        }
        sum0 += __shfl_xor_sync(0xffffffffu, sum0, 1);
        sum0 += __shfl_xor_sync(0xffffffffu, sum0, 2);
        sum1 += __shfl_xor_sync(0xffffffffu, sum1, 1);
        sum1 += __shfl_xor_sync(0xffffffffu, sum1, 2);
        float f0 = __expf(m0 - mn0), f1 = __expf(m1 - mn1);
        l0 = l0 * f0 + sum0; l1 = l1 * f1 + sum1;
        m0 = mn0; m1 = mn1;
#pragma unroll
        for (int nt = 0; nt < 8; nt++) {
            O[nt][0] *= f0; O[nt][1] *= f0; O[nt][2] *= f1; O[nt][3] *= f1;
        }

        // ---- O += P @ V ----
#pragma unroll
        for (int kt = 0; kt < 8; kt++) {
            uint32_t a[4];
            {
                float v0 = __shfl_sync(0xffffffffu, sc[kt][0], src_lo);
                float v1 = __shfl_sync(0xffffffffu, sc[kt][1], src_lo);
                a[0] = f2tf(odd ? v1 : v0);
                v0 = __shfl_sync(0xffffffffu, sc[kt][0], src_hi);
                v1 = __shfl_sync(0xffffffffu, sc[kt][1], src_hi);
                a[2] = f2tf(odd ? v1 : v0);
                v0 = __shfl_sync(0xffffffffu, sc[kt][2], src_lo);
                v1 = __shfl_sync(0xffffffffu, sc[kt][3], src_lo);
                a[1] = f2tf(odd ? v1 : v0);
                v0 = __shfl_sync(0xffffffffu, sc[kt][2], src_hi);
                v1 = __shfl_sync(0xffffffffu, sc[kt][3], src_hi);
                a[3] = f2tf(odd ? v1 : v0);
            }
#pragma unroll
            for (int nt = 0; nt < 8; nt++) {
                uint32_t b[2];
                b[0] = f2tf(v_s[(kt * 8 + lq) * 68 + nt * 8 + l4]);
                b[1] = f2tf(v_s[(kt * 8 + lq + 4) * 68 + nt * 8 + l4]);
                mma_tf32(O[nt], a, b);
            }
        }
        __syncthreads();
    }

    // ---- epilogue: y in (B,T,C) ----
    float inv0 = 1.f / l0, inv1 = 1.f / l1;
    int t0 = tt * 128 + wrow + l4;
#pragma unroll
    for (int nt = 0; nt < 8; nt++) {
        int cc = hh * 64 + nt * 8 + 2 * lq;
        *(float2*)&g_y[(size_t)(bb * T + t0) * C + cc] =
            make_float2(O[nt][0] * inv0, O[nt][1] * inv0);
        *(float2*)&g_y[(size_t)(bb * T + t0 + 8) * C + cc] =
            make_float2(O[nt][2] * inv1, O[nt][3] * inv1);
    }
}

// ================= launch =================
extern "C" void kernel_launch(void* const* d_in, const int* in_sizes, int n_in,
                              void* d_out, int out_size)
{
    (void)in_sizes; (void)n_in; (void)out_size;
    const float* x      = (const float*)d_in[0];
    const float* kcache = (const float*)d_in[1];
    const float* vcache = (const float*)d_in[2];
    const float* Wqkv   = (const float*)d_in[3];
    const float* bqkv   = (const float*)d_in[4];
    const float* Wproj  = (const float*)d_in[5];
    const float* bproj  = (const float*)d_in[6];
    float* out = (float*)d_out;

    cudaFuncSetAttribute(gemm_tc<NKV, true>, cudaFuncAttributeMaxDynamicSharedMemorySize, GEMM_SMEM);
    cudaFuncSetAttribute(gemm_tc<C, false>, cudaFuncAttributeMaxDynamicSharedMemorySize, GEMM_SMEM);
    cudaFuncSetAttribute(attn_tc, cudaFuncAttributeMaxDynamicSharedMemorySize, ATT_SMEM);

    gemm_tc<NKV, true><<<dim3(NKV / 128, M / 128), 128, GEMM_SMEM>>>(x, Wqkv, bqkv, nullptr);
    attn_tc<<<dim3(T / 128, H, B), 256, ATT_SMEM>>>(kcache, vcache);
    gemm_tc<C, false><<<dim3(C / 128, M / 128), 128, GEMM_SMEM>>>(nullptr, Wproj, bproj, out);
}